// round 16
// baseline (speedup 1.0000x reference)
#include <cuda_runtime.h>
#include <cstddef>
#include <cstdint>

#define Bz 32
#define Tt 4096
#define Uu 512

typedef unsigned long long u64;

// 256MB scratch: holds XW = x@w_x + b_h, overwritten in place by H during scan.
__device__ float g_xw[(size_t)Bz * Tt * Uu];
// per-chain monotonic counters (16 chains, 128B apart)
__device__ unsigned int g_ctr[16 * 32];

// ---------------------------------------------------------------------------
// Packed fp32x2 helpers
// ---------------------------------------------------------------------------
__device__ __forceinline__ u64 pack1(float v) {
    u64 r; asm("mov.b64 %0, {%1, %1};" : "=l"(r) : "f"(v)); return r;
}
__device__ __forceinline__ u64 pack2(float a, float b) {
    u64 r; asm("mov.b64 %0, {%1, %2};" : "=l"(r) : "f"(a), "f"(b)); return r;
}
__device__ __forceinline__ void unpack2(float& lo, float& hi, u64 v) {
    asm("mov.b64 {%0, %1}, %2;" : "=f"(lo), "=f"(hi) : "l"(v));
}
__device__ __forceinline__ u64 ffma2(u64 a, u64 b, u64 c) {
    u64 d;
    asm("fma.rn.f32x2 %0, %1, %2, %3;" : "=l"(d) : "l"(a), "l"(b), "l"(c));
    return d;
}
__device__ __forceinline__ u64 add2(u64 a, u64 b) {
    u64 d;
    asm("add.rn.f32x2 %0, %1, %2;" : "=l"(d) : "l"(a), "l"(b));
    return d;
}

__device__ __forceinline__ float my_tanh(float x) {
    float ax = fabsf(x);
    if (ax < 0.125f) {
        float x2 = x * x;
        return x * (1.f + x2 * (-0.333333333f + x2 * 0.133333333f));
    }
    float e = __expf(2.f * ax);
    float r = 1.f - 2.f / (1.f + e);
    return copysignf(r, x);
}

// ---------------------------------------------------------------------------
// SGEMM with bias, double-buffered SMEM, packed-fp32 (FFMA2) inner loop.
// (proven version; resets 16 chain counters.)
// ---------------------------------------------------------------------------
__global__ __launch_bounds__(256) void sgemm_bias(
    const float* __restrict__ A, const float* __restrict__ Bm,
    const float* __restrict__ bias, float* __restrict__ C,
    unsigned int* __restrict__ rctr)
{
    __shared__ float As[2][16][132];
    __shared__ float Bs[2][16][128];
    const int tid = threadIdx.x;
    const int tx = tid & 15, ty = tid >> 4;
    const size_t row0 = (size_t)blockIdx.y * 128;
    const int col0 = blockIdx.x * 128;

    if (rctr && blockIdx.x == 0 && blockIdx.y == 0 && tid < 16)
        rctr[tid * 32] = 0u;

    const int f0 = tid, f1 = tid + 256;
    const int ar0 = f0 >> 2, ak0 = (f0 & 3) << 2;
    const int ar1 = f1 >> 2, ak1 = (f1 & 3) << 2;
    const int br0 = f0 >> 5, bc0 = (f0 & 31) << 2;
    const int br1 = f1 >> 5, bc1 = (f1 & 31) << 2;

    float4 pa0, pa1, pb0, pb1;

    pa0 = *(const float4*)&A[(row0 + ar0) * 512 + 0 + ak0];
    pa1 = *(const float4*)&A[(row0 + ar1) * 512 + 0 + ak1];
    pb0 = *(const float4*)&Bm[(size_t)(0 + br0) * 512 + col0 + bc0];
    pb1 = *(const float4*)&Bm[(size_t)(0 + br1) * 512 + col0 + bc1];
    As[0][ak0 + 0][ar0] = pa0.x; As[0][ak0 + 1][ar0] = pa0.y;
    As[0][ak0 + 2][ar0] = pa0.z; As[0][ak0 + 3][ar0] = pa0.w;
    As[0][ak1 + 0][ar1] = pa1.x; As[0][ak1 + 1][ar1] = pa1.y;
    As[0][ak1 + 2][ar1] = pa1.z; As[0][ak1 + 3][ar1] = pa1.w;
    *(float4*)&Bs[0][br0][bc0] = pb0;
    *(float4*)&Bs[0][br1][bc1] = pb1;
    __syncthreads();

    u64 acc2[8][4];
#pragma unroll
    for (int i = 0; i < 8; i++)
#pragma unroll
        for (int p = 0; p < 4; p++) acc2[i][p] = pack1(0.f);

    for (int k0 = 0; k0 < 512; k0 += 16) {
        const int cur = (k0 >> 4) & 1;
        const bool more = (k0 + 16) < 512;
        if (more) {
            pa0 = *(const float4*)&A[(row0 + ar0) * 512 + k0 + 16 + ak0];
            pa1 = *(const float4*)&A[(row0 + ar1) * 512 + k0 + 16 + ak1];
            pb0 = *(const float4*)&Bm[(size_t)(k0 + 16 + br0) * 512 + col0 + bc0];
            pb1 = *(const float4*)&Bm[(size_t)(k0 + 16 + br1) * 512 + col0 + bc1];
        }
#pragma unroll
        for (int k = 0; k < 16; k++) {
            float a[8];
            *(float4*)&a[0] = *(const float4*)&As[cur][k][ty * 8];
            *(float4*)&a[4] = *(const float4*)&As[cur][k][ty * 8 + 4];
            ulonglong2 bq0 = *(const ulonglong2*)&Bs[cur][k][tx * 8];
            ulonglong2 bq1 = *(const ulonglong2*)&Bs[cur][k][tx * 8 + 4];
            u64 bp[4] = {bq0.x, bq0.y, bq1.x, bq1.y};
#pragma unroll
            for (int i = 0; i < 8; i++) {
                u64 ad = pack1(a[i]);
#pragma unroll
                for (int p = 0; p < 4; p++)
                    acc2[i][p] = ffma2(ad, bp[p], acc2[i][p]);
            }
        }
        if (more) {
            const int nxt = cur ^ 1;
            As[nxt][ak0 + 0][ar0] = pa0.x; As[nxt][ak0 + 1][ar0] = pa0.y;
            As[nxt][ak0 + 2][ar0] = pa0.z; As[nxt][ak0 + 3][ar0] = pa0.w;
            As[nxt][ak1 + 0][ar1] = pa1.x; As[nxt][ak1 + 1][ar1] = pa1.y;
            As[nxt][ak1 + 2][ar1] = pa1.z; As[nxt][ak1 + 3][ar1] = pa1.w;
            *(float4*)&Bs[nxt][br0][bc0] = pb0;
            *(float4*)&Bs[nxt][br1][bc1] = pb1;
            __syncthreads();
        }
    }

    float bj[8];
    *(float4*)&bj[0] = *(const float4*)&bias[col0 + tx * 8];
    *(float4*)&bj[4] = *(const float4*)&bias[col0 + tx * 8 + 4];
#pragma unroll
    for (int i = 0; i < 8; i++) {
        float c[8];
#pragma unroll
        for (int p = 0; p < 4; p++)
            unpack2(c[2 * p], c[2 * p + 1], acc2[i][p]);
        size_t r = row0 + ty * 8 + i;
        float4 v0 = make_float4(c[0] + bj[0], c[1] + bj[1],
                                c[2] + bj[2], c[3] + bj[3]);
        float4 v1 = make_float4(c[4] + bj[4], c[5] + bj[5],
                                c[6] + bj[6], c[7] + bj[7]);
        *(float4*)&C[r * 512 + col0 + tx * 8] = v0;
        *(float4*)&C[r * 512 + col0 + tx * 8 + 4] = v1;
    }
}

// ---------------------------------------------------------------------------
// Recurrent scan v13: dual-chain pipelined.
// 16 chains x 2 batches; chain c owns batches {2c, 2c+1}, counter g_ctr[c*32].
// Physical CTA p (128 total): cig = p&15 -> units [32cig, 32cig+32);
// pr = p>>4 -> serves chains A=2pr, B=2pr+1 (same unit slice, shared wreg).
// Per iteration: compute/store/release A, compute/store/release B (A's
// barrier hides under B), spin A, reload A, spin B (hides under reload A),
// reload B. w register-resident as (w,w) u64; h as (h_b0,h_b1) u64 broadcast.
// ---------------------------------------------------------------------------
__global__ __launch_bounds__(256, 1) void rnn_scan13(
    const float* __restrict__ w_h, const float* __restrict__ h0)
{
    __shared__ u64 bufA[512];      // (h[2c][d], h[2c+1][d])
    __shared__ u64 bufB[512];
    __shared__ u64 psum[256];      // [warp*32 + lane]

    const int tid  = threadIdx.x;
    const int warp = tid >> 5;
    const int lane = tid & 31;
    const int cig  = blockIdx.x & 15;
    const int pr   = blockIdx.x >> 4;      // 0..7
    const int chA  = 2 * pr, chB = 2 * pr + 1;
    const int u0   = cig << 5;

    // ---- register-resident w: 64 d-values for unit (u0+lane), packed (w,w)
    u64 wreg[64];
#pragma unroll
    for (int j = 0; j < 64; j++)
        wreg[j] = pack1(w_h[(size_t)(warp * 64 + j) * 512 + u0 + lane]);

    unsigned int* ctrA = &g_ctr[chA * 32];
    unsigned int* ctrB = &g_ctr[chB * 32];

    // writers (tid < 64): unit ul = tid>>1, batch-in-chain bq = tid&1
    size_t oA = 0, oB = 0;
    float xwA = 0.f, xwB = 0.f;
    if (tid < 64) {
        int ul = tid >> 1, bq = tid & 1;
        oA = ((size_t)(chA * 2 + bq) * Tt) * Uu + u0 + ul;
        oB = ((size_t)(chB * 2 + bq) * Tt) * Uu + u0 + ul;
        xwA = g_xw[oA];                  // xw for t = 0
        xwB = g_xw[oB];
    }

    // init h_{-1} = h0 for both chains
#pragma unroll
    for (int r = 0; r < 2; r++) {
        int d = tid + r * 256;
        u64 v = pack1(h0[d]);
        bufA[d] = v;
        bufB[d] = v;
    }
    __syncthreads();

    for (int t = 0; t < Tt; t++) {
        // ======== chain A: compute + publish ========
        {
            const u64* hp = &bufA[warp * 64];
            u64 a0 = pack1(0.f), a1 = pack1(0.f);
#pragma unroll
            for (int j = 0; j < 64; j += 2) {
                a0 = ffma2(wreg[j], hp[j], a0);
                a1 = ffma2(wreg[j + 1], hp[j + 1], a1);
            }
            psum[warp * 32 + lane] = add2(a0, a1);
        }
        __syncthreads();                                        // S1
        if (tid < 64) {
            const float* pf = (const float*)psum;
            float s = 0.f;
#pragma unroll
            for (int w = 0; w < 8; w++) s += pf[w * 64 + tid];
            float val = my_tanh(s + xwA);
            g_xw[oA + (size_t)t * Uu] = val;
            if (t + 1 < Tt) xwA = g_xw[oA + (size_t)(t + 1) * Uu];
        }
        __syncthreads();                                        // S2
        if (tid == 0)
            asm volatile("red.release.gpu.global.add.u32 [%0], %1;"
                         :: "l"(ctrA), "r"(1u) : "memory");

        // ======== chain B: compute + publish (hides A's barrier) ========
        {
            const u64* hp = &bufB[warp * 64];
            u64 a0 = pack1(0.f), a1 = pack1(0.f);
#pragma unroll
            for (int j = 0; j < 64; j += 2) {
                a0 = ffma2(wreg[j], hp[j], a0);
                a1 = ffma2(wreg[j + 1], hp[j + 1], a1);
            }
            psum[warp * 32 + lane] = add2(a0, a1);
        }
        __syncthreads();                                        // S3
        if (tid < 64) {
            const float* pf = (const float*)psum;
            float s = 0.f;
#pragma unroll
            for (int w = 0; w < 8; w++) s += pf[w * 64 + tid];
            float val = my_tanh(s + xwB);
            g_xw[oB + (size_t)t * Uu] = val;
            if (t + 1 < Tt) xwB = g_xw[oB + (size_t)(t + 1) * Uu];
        }
        __syncthreads();                                        // S4
        if (tid == 0)
            asm volatile("red.release.gpu.global.add.u32 [%0], %1;"
                         :: "l"(ctrB), "r"(1u) : "memory");

        if (t + 1 == Tt) break;
        const unsigned int target = (unsigned int)(16 * (t + 1));

        // ======== wait A, reload bufA = hA_t ========
        if (tid == 0) {
            unsigned int v;
            do {
                asm volatile("ld.global.acquire.gpu.u32 %0, [%1];"
                             : "=r"(v) : "l"(ctrA));
            } while (v < target);
        }
        __syncthreads();                                        // S5
#pragma unroll
        for (int r = 0; r < 2; r++) {
            int d = tid + r * 256;
            size_t rb = (size_t)t * Uu + d;
            float v0 = g_xw[(size_t)(chA * 2 + 0) * Tt * Uu + rb];
            float v1 = g_xw[(size_t)(chA * 2 + 1) * Tt * Uu + rb];
            bufA[d] = pack2(v0, v1);
        }

        // ======== wait B (hides under reload A), reload bufB ========
        if (tid == 0) {
            unsigned int v;
            do {
                asm volatile("ld.global.acquire.gpu.u32 %0, [%1];"
                             : "=r"(v) : "l"(ctrB));
            } while (v < target);
        }
        __syncthreads();                                        // S6
#pragma unroll
        for (int r = 0; r < 2; r++) {
            int d = tid + r * 256;
            size_t rb = (size_t)t * Uu + d;
            float v0 = g_xw[(size_t)(chB * 2 + 0) * Tt * Uu + rb];
            float v1 = g_xw[(size_t)(chB * 2 + 1) * Tt * Uu + rb];
            bufB[d] = pack2(v0, v1);
        }
        __syncthreads();                                        // S7
    }
}

// ---------------------------------------------------------------------------
// h_final = H[:, T-1, :]
__global__ void copy_hfinal(float* __restrict__ out) {
    int i = blockIdx.x * 256 + threadIdx.x;
    if (i < Bz * Uu) {
        int b = i >> 9, u = i & 511;
        out[(size_t)Bz * Tt * Uu + i] =
            g_xw[((size_t)b * Tt + (Tt - 1)) * Uu + u];
    }
}

// ---------------------------------------------------------------------------
extern "C" void kernel_launch(void* const* d_in, const int* in_sizes, int n_in,
                              void* d_out, int out_size) {
    const float* x   = (const float*)d_in[0];
    const float* w_h = (const float*)d_in[1];
    const float* w_x = (const float*)d_in[2];
    const float* w_y = (const float*)d_in[3];
    const float* b_h = (const float*)d_in[4];
    const float* b_y = (const float*)d_in[5];
    const float* h0  = (const float*)d_in[6];
    float* out = (float*)d_out;

    float* xw = nullptr;
    unsigned int* ctr = nullptr;
    cudaGetSymbolAddress((void**)&xw, g_xw);
    cudaGetSymbolAddress((void**)&ctr, g_ctr);

    dim3 gg(4, 1024);

    // Phase 1: XW = x @ w_x + b_h  (also resets the 16 chain counters)
    sgemm_bias<<<gg, 256>>>(x, w_x, b_h, xw, ctr);
    // Phase 2: dual-chain pipelined scan, H overwrites XW in place
    rnn_scan13<<<128, 256>>>(w_h, h0);
    // Phase 3: Y = H @ w_y + b_y
    sgemm_bias<<<gg, 256>>>(xw, w_y, b_y, out, nullptr);
    // h_final = H[:, T-1, :]
    copy_hfinal<<<64, 256>>>(out);
}

// round 17
// speedup vs baseline: 1.1490x; 1.1490x over previous
#include <cuda_runtime.h>
#include <cstddef>
#include <cstdint>

#define Bz 32
#define Tt 4096
#define Uu 512

typedef unsigned long long u64;

// 256MB scratch: holds XW = x@w_x + b_h, overwritten in place by H during scan.
__device__ float g_xw[(size_t)Bz * Tt * Uu];
// per-group monotonic counters (8 groups used, 128B apart)
__device__ unsigned int g_ctr[16 * 32];

// ---------------------------------------------------------------------------
// Packed fp32x2 helpers
// ---------------------------------------------------------------------------
__device__ __forceinline__ u64 pack1(float v) {
    u64 r; asm("mov.b64 %0, {%1, %1};" : "=l"(r) : "f"(v)); return r;
}
__device__ __forceinline__ void unpack2(float& lo, float& hi, u64 v) {
    asm("mov.b64 {%0, %1}, %2;" : "=f"(lo), "=f"(hi) : "l"(v));
}
__device__ __forceinline__ u64 ffma2(u64 a, u64 b, u64 c) {
    u64 d;
    asm("fma.rn.f32x2 %0, %1, %2, %3;" : "=l"(d) : "l"(a), "l"(b), "l"(c));
    return d;
}
__device__ __forceinline__ u64 add2(u64 a, u64 b) {
    u64 d;
    asm("add.rn.f32x2 %0, %1, %2;" : "=l"(d) : "l"(a), "l"(b));
    return d;
}

__device__ __forceinline__ float my_tanh(float x) {
    float ax = fabsf(x);
    if (ax < 0.125f) {
        float x2 = x * x;
        return x * (1.f + x2 * (-0.333333333f + x2 * 0.133333333f));
    }
    float e = __expf(2.f * ax);
    float r = 1.f - 2.f / (1.f + e);
    return copysignf(r, x);
}

// ---------------------------------------------------------------------------
// SGEMM with bias, double-buffered SMEM, packed-fp32 (FFMA2) inner loop.
// (proven version; resets counters.)
// ---------------------------------------------------------------------------
__global__ __launch_bounds__(256) void sgemm_bias(
    const float* __restrict__ A, const float* __restrict__ Bm,
    const float* __restrict__ bias, float* __restrict__ C,
    unsigned int* __restrict__ rctr)
{
    __shared__ float As[2][16][132];
    __shared__ float Bs[2][16][128];
    const int tid = threadIdx.x;
    const int tx = tid & 15, ty = tid >> 4;
    const size_t row0 = (size_t)blockIdx.y * 128;
    const int col0 = blockIdx.x * 128;

    if (rctr && blockIdx.x == 0 && blockIdx.y == 0 && tid < 16)
        rctr[tid * 32] = 0u;

    const int f0 = tid, f1 = tid + 256;
    const int ar0 = f0 >> 2, ak0 = (f0 & 3) << 2;
    const int ar1 = f1 >> 2, ak1 = (f1 & 3) << 2;
    const int br0 = f0 >> 5, bc0 = (f0 & 31) << 2;
    const int br1 = f1 >> 5, bc1 = (f1 & 31) << 2;

    float4 pa0, pa1, pb0, pb1;

    pa0 = *(const float4*)&A[(row0 + ar0) * 512 + 0 + ak0];
    pa1 = *(const float4*)&A[(row0 + ar1) * 512 + 0 + ak1];
    pb0 = *(const float4*)&Bm[(size_t)(0 + br0) * 512 + col0 + bc0];
    pb1 = *(const float4*)&Bm[(size_t)(0 + br1) * 512 + col0 + bc1];
    As[0][ak0 + 0][ar0] = pa0.x; As[0][ak0 + 1][ar0] = pa0.y;
    As[0][ak0 + 2][ar0] = pa0.z; As[0][ak0 + 3][ar0] = pa0.w;
    As[0][ak1 + 0][ar1] = pa1.x; As[0][ak1 + 1][ar1] = pa1.y;
    As[0][ak1 + 2][ar1] = pa1.z; As[0][ak1 + 3][ar1] = pa1.w;
    *(float4*)&Bs[0][br0][bc0] = pb0;
    *(float4*)&Bs[0][br1][bc1] = pb1;
    __syncthreads();

    u64 acc2[8][4];
#pragma unroll
    for (int i = 0; i < 8; i++)
#pragma unroll
        for (int p = 0; p < 4; p++) acc2[i][p] = pack1(0.f);

    for (int k0 = 0; k0 < 512; k0 += 16) {
        const int cur = (k0 >> 4) & 1;
        const bool more = (k0 + 16) < 512;
        if (more) {
            pa0 = *(const float4*)&A[(row0 + ar0) * 512 + k0 + 16 + ak0];
            pa1 = *(const float4*)&A[(row0 + ar1) * 512 + k0 + 16 + ak1];
            pb0 = *(const float4*)&Bm[(size_t)(k0 + 16 + br0) * 512 + col0 + bc0];
            pb1 = *(const float4*)&Bm[(size_t)(k0 + 16 + br1) * 512 + col0 + bc1];
        }
#pragma unroll
        for (int k = 0; k < 16; k++) {
            float a[8];
            *(float4*)&a[0] = *(const float4*)&As[cur][k][ty * 8];
            *(float4*)&a[4] = *(const float4*)&As[cur][k][ty * 8 + 4];
            ulonglong2 bq0 = *(const ulonglong2*)&Bs[cur][k][tx * 8];
            ulonglong2 bq1 = *(const ulonglong2*)&Bs[cur][k][tx * 8 + 4];
            u64 bp[4] = {bq0.x, bq0.y, bq1.x, bq1.y};
#pragma unroll
            for (int i = 0; i < 8; i++) {
                u64 ad = pack1(a[i]);
#pragma unroll
                for (int p = 0; p < 4; p++)
                    acc2[i][p] = ffma2(ad, bp[p], acc2[i][p]);
            }
        }
        if (more) {
            const int nxt = cur ^ 1;
            As[nxt][ak0 + 0][ar0] = pa0.x; As[nxt][ak0 + 1][ar0] = pa0.y;
            As[nxt][ak0 + 2][ar0] = pa0.z; As[nxt][ak0 + 3][ar0] = pa0.w;
            As[nxt][ak1 + 0][ar1] = pa1.x; As[nxt][ak1 + 1][ar1] = pa1.y;
            As[nxt][ak1 + 2][ar1] = pa1.z; As[nxt][ak1 + 3][ar1] = pa1.w;
            *(float4*)&Bs[nxt][br0][bc0] = pb0;
            *(float4*)&Bs[nxt][br1][bc1] = pb1;
            __syncthreads();
        }
    }

    float bj[8];
    *(float4*)&bj[0] = *(const float4*)&bias[col0 + tx * 8];
    *(float4*)&bj[4] = *(const float4*)&bias[col0 + tx * 8 + 4];
#pragma unroll
    for (int i = 0; i < 8; i++) {
        float c[8];
#pragma unroll
        for (int p = 0; p < 4; p++)
            unpack2(c[2 * p], c[2 * p + 1], acc2[i][p]);
        size_t r = row0 + ty * 8 + i;
        float4 v0 = make_float4(c[0] + bj[0], c[1] + bj[1],
                                c[2] + bj[2], c[3] + bj[3]);
        float4 v1 = make_float4(c[4] + bj[4], c[5] + bj[5],
                                c[6] + bj[6], c[7] + bj[7]);
        *(float4*)&C[r * 512 + col0 + tx * 8] = v0;
        *(float4*)&C[r * 512 + col0 + tx * 8 + 4] = v1;
    }
}

// ---------------------------------------------------------------------------
// Recurrent scan v14 = v12's arithmetic + warp-autonomous barrier/reload.
// 8 groups x 16 CTAs. Group g owns batches [4g,4g+4); CTA c owns units
// [32c,32c+32). Warp w owns d in [64w,64w+64); lane = unit; w register-
// resident pre-packed (w,w).
// Per step, ONE full __syncthreads (after psum). Writers (warps 0-3) do the
// reduce/tanh/h-store, sync among themselves via bar.sync 1,128, tid0
// releases. EVERY warp then polls the group counter itself (lane0 acquire +
// syncwarp), reloads ONLY its own 64-d hp block, and proceeds straight to
// compute. Warps 4-7 never wait on the writer tail.
// ---------------------------------------------------------------------------
__global__ __launch_bounds__(256, 1) void rnn_scan14(
    const float* __restrict__ w_h, const float* __restrict__ h0)
{
    __shared__ float4 hp_s[512];          // 8KB: (b0,b1,b2,b3) per d
    __shared__ ulonglong2 psum2[256];     // 4KB: [warp*32 + lane]

    const int tid  = threadIdx.x;
    const int warp = tid >> 5;
    const int lane = tid & 31;
    const int grp  = blockIdx.x >> 4;     // 0..7
    const int cig  = blockIdx.x & 15;     // 0..15
    const int b0   = grp << 2;
    const int u0   = cig << 5;

    // ---- load this thread's 64 w values into pre-packed registers ----
    u64 wreg[64];
#pragma unroll
    for (int j = 0; j < 64; j++)
        wreg[j] = pack1(w_h[(size_t)(warp * 64 + j) * 512 + u0 + lane]);

    unsigned int* ctr = &g_ctr[grp * 32];

    // writer threads (tid < 128): output = (unit ul, batch bq)
    size_t oidx = 0;
    float xw_pf = 0.f;
    if (tid < 128) {
        int ul = tid >> 2, bq = tid & 3;
        oidx = ((size_t)(b0 + bq) * Tt) * Uu + u0 + ul;
        xw_pf = g_xw[oidx];               // xw for t = 0
    }

    // ---- init h_{-1} = h0 ----
#pragma unroll
    for (int r = 0; r < 2; r++) {
        int d = tid + r * 256;
        float v = h0[d];
        hp_s[d] = make_float4(v, v, v, v);
    }
    __syncthreads();

    for (int t = 0; t < Tt; t++) {
        // ---- broadcast-h FFMA2 dot: own 64-d block, ILP-2 ----
        const ulonglong2* hp = (const ulonglong2*)&hp_s[warp * 64];
        u64 a01a = pack1(0.f), a01b = pack1(0.f);
        u64 a23a = pack1(0.f), a23b = pack1(0.f);
#pragma unroll
        for (int j = 0; j < 64; j += 2) {
            ulonglong2 q0 = hp[j];
            ulonglong2 q1 = hp[j + 1];
            a01a = ffma2(wreg[j], q0.x, a01a);
            a23a = ffma2(wreg[j], q0.y, a23a);
            a01b = ffma2(wreg[j + 1], q1.x, a01b);
            a23b = ffma2(wreg[j + 1], q1.y, a23b);
        }
        ulonglong2 mine;
        mine.x = add2(a01a, a01b);
        mine.y = add2(a23a, a23b);
        psum2[warp * 32 + lane] = mine;
        __syncthreads();      // the ONE full sync: all psum visible

        // ---- writers: final reduce, tanh, persist h_t, prefetch xw ----
        if (tid < 128) {
            const float* pf = (const float*)psum2;  // idx: w*128 + ul*4 + bq
            float s = 0.f;
#pragma unroll
            for (int w = 0; w < 8; w++) s += pf[w * 128 + tid];
            float val = my_tanh(s + xw_pf);
            g_xw[oidx + (size_t)t * Uu] = val;
            if (t + 1 < Tt)
                xw_pf = g_xw[oidx + (size_t)(t + 1) * Uu];
            // writers sync among themselves; then tid0 releases the group ctr
            asm volatile("bar.sync 1, 128;" ::: "memory");
            if (tid == 0)
                asm volatile("red.release.gpu.global.add.u32 [%0], %1;"
                             :: "l"(ctr), "r"(1u) : "memory");
        }

        if (t + 1 == Tt) break;

        // ---- every warp: poll counter, reload OWN 64-d hp block ----
        if (lane == 0) {
            unsigned int target = (unsigned int)(16 * (t + 1));
            unsigned int v;
            do {
                asm volatile("ld.global.acquire.gpu.u32 %0, [%1];"
                             : "=r"(v) : "l"(ctr));
            } while (v < target);
        }
        __syncwarp();
#pragma unroll
        for (int r = 0; r < 2; r++) {
            int d = warp * 64 + lane + r * 32;
            size_t rb = (size_t)t * Uu + d;
            hp_s[d] = make_float4(
                g_xw[(size_t)(b0 + 0) * Tt * Uu + rb],
                g_xw[(size_t)(b0 + 1) * Tt * Uu + rb],
                g_xw[(size_t)(b0 + 2) * Tt * Uu + rb],
                g_xw[(size_t)(b0 + 3) * Tt * Uu + rb]);
        }
        __syncwarp();         // own block ready; straight into compute
    }
}

// ---------------------------------------------------------------------------
// h_final = H[:, T-1, :]
__global__ void copy_hfinal(float* __restrict__ out) {
    int i = blockIdx.x * 256 + threadIdx.x;
    if (i < Bz * Uu) {
        int b = i >> 9, u = i & 511;
        out[(size_t)Bz * Tt * Uu + i] =
            g_xw[((size_t)b * Tt + (Tt - 1)) * Uu + u];
    }
}

// ---------------------------------------------------------------------------
extern "C" void kernel_launch(void* const* d_in, const int* in_sizes, int n_in,
                              void* d_out, int out_size) {
    const float* x   = (const float*)d_in[0];
    const float* w_h = (const float*)d_in[1];
    const float* w_x = (const float*)d_in[2];
    const float* w_y = (const float*)d_in[3];
    const float* b_h = (const float*)d_in[4];
    const float* b_y = (const float*)d_in[5];
    const float* h0  = (const float*)d_in[6];
    float* out = (float*)d_out;

    float* xw = nullptr;
    unsigned int* ctr = nullptr;
    cudaGetSymbolAddress((void**)&xw, g_xw);
    cudaGetSymbolAddress((void**)&ctr, g_ctr);

    dim3 gg(4, 1024);

    // Phase 1: XW = x @ w_x + b_h  (also resets scan counters)
    sgemm_bias<<<gg, 256>>>(x, w_x, b_h, xw, ctr);
    // Phase 2: sequential scan (128 CTAs, 8 groups), H overwrites XW in place
    rnn_scan14<<<128, 256>>>(w_h, h0);
    // Phase 3: Y = H @ w_y + b_y
    sgemm_bias<<<gg, 256>>>(xw, w_y, b_y, out, nullptr);
    // h_final = H[:, T-1, :]
    copy_hfinal<<<64, 256>>>(out);
}